// round 12
// baseline (speedup 1.0000x reference)
#include <cuda_runtime.h>
#include <cuda_fp16.h>
#include <cstdint>

#define N_NODES 100000
#define N_FEAT  512
#define N_CLASS 64
#define N_EDGES 3200000

#define GBM 128           // GEMM rows per CTA
#define NCHUNK 8          // 512/64
#define APAD 72           // padded halves per A/B smem row (144B, conflict-free)

#define A_BUF_BYTES (GBM * APAD * 2)       // 18432
#define B_BUF_BYTES (N_CLASS * APAD * 2)   //  9216
#define SMEM_B_OFF  (2 * A_BUF_BYTES)      // 36864
#define GEMM_SMEM   (2 * A_BUF_BYTES + 2 * B_BUF_BYTES)  // 55296

#define HIST_BLOCKS ((N_EDGES + 255) / 256)   // 12500

// ---------------- scratch (static device globals; zero-initialized) ----------------
__device__ __half2  g_hh0[(size_t)N_NODES * 32];    // 12.8 MB
__device__ __half2  g_hh1[(size_t)N_NODES * 32];    // 12.8 MB
__device__ __half2  g_wt[64 * 256];                 // Wt[n][k] fp16: 64 x 512 (64 KB)
__device__ int   g_count[N_NODES];                  // zero at load; self-cleared each launch
__device__ int   g_row_start[N_NODES + 1];
__device__ int   g_cursor[N_NODES];
__device__ uint2 g_csr[N_EDGES];
__device__ int   g_block_sums[64];

// ---------------- hist + wconv (merged): blocks [0,64) wconv, rest hist ----------------
__global__ void hist_wconv_kernel(const int* __restrict__ erow,
                                  const float* __restrict__ W) {
    int b = blockIdx.x;
    int t = threadIdx.x;
    if (b < 64) {
        // W [K][N] -> Wt [N][K] fp16
        int idx = b * 256 + t;      // 0..16383
        int n  = idx >> 8;          // 0..63
        int k2 = idx & 255;         // pairs of k
        int k = k2 * 2;
        float w0 = W[(size_t)k * N_CLASS + n];
        float w1 = W[(size_t)(k + 1) * N_CLASS + n];
        g_wt[n * 256 + k2] = __floats2half2_rn(w0, w1);
    } else {
        int e = (b - 64) * 256 + t;
        if (e < N_EDGES) atomicAdd(&g_count[erow[e]], 1);
    }
}

// ---------------- scan pass1: per-block sums (25 blocks x 1024 x 4) ----------------
__global__ void scan_pass1_kernel() {
    __shared__ int wsum[32];
    int t = threadIdx.x;
    int base = blockIdx.x * 4096;
    int s = 0;
#pragma unroll
    for (int i = 0; i < 4; i++) {
        int idx = base + t * 4 + i;
        if (idx < N_NODES) s += g_count[idx];
    }
#pragma unroll
    for (int o = 16; o; o >>= 1) s += __shfl_down_sync(0xffffffffu, s, o);
    if ((t & 31) == 0) wsum[t >> 5] = s;
    __syncthreads();
    if (t < 32) {
        int v = wsum[t];
#pragma unroll
        for (int o = 16; o; o >>= 1) v += __shfl_down_sync(0xffffffffu, v, o);
        if (t == 0) g_block_sums[blockIdx.x] = v;
    }
}

// ---------------- scan pass2+3 merged: each block scans the 25 sums itself ----------------
__global__ void scan_pass23_kernel() {
    __shared__ int woff[32];
    __shared__ int s_boff;
    int t = threadIdx.x, lane = t & 31, wid = t >> 5;

    if (t < 32) {
        int v = (t < 25) ? g_block_sums[t] : 0;
        int x = v;
#pragma unroll
        for (int o = 1; o < 32; o <<= 1) {
            int y = __shfl_up_sync(0xffffffffu, x, o);
            if (t >= o) x += y;
        }
        if (t == (int)blockIdx.x) s_boff = x - v;        // exclusive offset for this block
        if (blockIdx.x == 0 && t == 24) g_row_start[N_NODES] = x;   // grand total
    }
    __syncthreads();

    int base = blockIdx.x * 4096;
    int v[4];
    int s = 0;
#pragma unroll
    for (int i = 0; i < 4; i++) {
        int idx = base + t * 4 + i;
        if (idx < N_NODES) {
            v[i] = g_count[idx];
            g_count[idx] = 0;        // self-clear for the next launch (deterministic replays)
        } else v[i] = 0;
        s += v[i];
    }
    int x = s;
#pragma unroll
    for (int o = 1; o < 32; o <<= 1) {
        int y = __shfl_up_sync(0xffffffffu, x, o);
        if (lane >= o) x += y;
    }
    if (lane == 31) woff[wid] = x;
    __syncthreads();
    if (wid == 0) {
        int w = woff[lane];
        int xw = w;
#pragma unroll
        for (int o = 1; o < 32; o <<= 1) {
            int y = __shfl_up_sync(0xffffffffu, xw, o);
            if (lane >= o) xw += y;
        }
        woff[lane] = xw - w;
    }
    __syncthreads();
    int off = s_boff + woff[wid] + (x - s);
#pragma unroll
    for (int i = 0; i < 4; i++) {
        int idx = base + t * 4 + i;
        if (idx < N_NODES) {
            g_row_start[idx] = off;
            g_cursor[idx] = off;
        }
        off += v[i];
    }
}

__global__ void fill_kernel(const int* __restrict__ erow,
                            const int* __restrict__ ecol,
                            const float* __restrict__ eval) {
    int e = blockIdx.x * blockDim.x + threadIdx.x;
    if (e < N_EDGES) {
        int pos = atomicAdd(&g_cursor[erow[e]], 1);
        g_csr[pos] = make_uint2((unsigned)ecol[e], __float_as_uint(eval[e]));
    }
}

// ---------------- pipelined HMMA GEMM, 32x32 warp tiles, coalesced A loads ----------------
// thread t handles chunk float4 indices f4 = t + 256*i: row = f4>>4, c4 = f4&15.
// 16 adjacent lanes read one row's contiguous 256B -> 4 L1 wavefronts per LDG.128.
__device__ __forceinline__ void ld_a(float4* areg, const float4* __restrict__ Xf4,
                                     int c, int t, int block_row) {
#pragma unroll
    for (int i = 0; i < 8; i++) {
        int f4 = t + 256 * i;
        int row = f4 >> 4, c4 = f4 & 15;
        int gr = block_row + row;
        areg[i] = (gr < N_NODES) ? Xf4[(size_t)gr * 128 + c * 16 + c4]
                                 : make_float4(0.f, 0.f, 0.f, 0.f);
    }
}

// STS.64 per element; with 144B row pad both half-warp phases hit 32 distinct banks.
__device__ __forceinline__ void sts_a(uint32_t abuf_base, int t, const float4* areg) {
#pragma unroll
    for (int i = 0; i < 8; i++) {
        int f4 = t + 256 * i;
        int row = f4 >> 4, c4 = f4 & 15;
        __half2 q0 = __floats2half2_rn(areg[i].x, areg[i].y);
        __half2 q1 = __floats2half2_rn(areg[i].z, areg[i].w);
        uint32_t addr = abuf_base + (uint32_t)row * (APAD * 2) + c4 * 8;
        asm volatile("st.shared.v2.b32 [%0], {%1, %2};"
                     :: "r"(addr), "r"(*(uint32_t*)&q0), "r"(*(uint32_t*)&q1)
                     : "memory");
    }
}

__device__ __forceinline__ void cp_b(uint32_t smem_base, int c, int buf, int t) {
    int n  = t >> 2;
    int sg = t & 3;
    const __half2* src = g_wt + n * 256 + c * 32 + sg * 4;
    uint32_t dst = smem_base + SMEM_B_OFF + buf * B_BUF_BYTES
                 + (uint32_t)n * (APAD * 2) + sg * 16;
    asm volatile("cp.async.ca.shared.global [%0], [%1], 16;" :: "r"(dst), "l"(src) : "memory");
    asm volatile("cp.async.ca.shared.global [%0], [%1], 16;" :: "r"(dst + 64), "l"(src + 16) : "memory");
    asm volatile("cp.async.commit_group;" ::: "memory");
}

__global__ void __launch_bounds__(256, 2) gemm_mma_kernel(const float* __restrict__ X) {
    extern __shared__ __align__(16) unsigned char smem_raw[];
    uint32_t smem_base;
    asm("{ .reg .u64 t; cvta.to.shared.u64 t, %1; cvt.u32.u64 %0, t; }"
        : "=r"(smem_base) : "l"(smem_raw));

    int t = threadIdx.x;
    int wid = t >> 5, lane = t & 31;
    int block_row = blockIdx.x * GBM;
    const float4* Xf4 = (const float4*)X;

    // warp tile: 32 rows x 32 cols. wm = M-group (0-3), wn = N-group (0-1)
    int wm = wid >> 1, wn = wid & 1;

    float acc[8][4];
#pragma unroll
    for (int i = 0; i < 8; i++)
#pragma unroll
        for (int j = 0; j < 4; j++) acc[i][j] = 0.f;

    // per-lane ldmatrix base addresses (buf 0)
    int a_row = wm * 32 + ((lane >> 3) & 1) * 8 + (lane & 7);
    int a_k8  = (lane >> 4) * 8;
    uint32_t a_base0 = smem_base + (uint32_t)a_row * (APAD * 2) + a_k8 * 2;
    int b_q = lane >> 3, b_l = lane & 7;
    int b_rowoff = wn * 32 + (b_q >> 1) * 8 + b_l;
    int b_k8 = (b_q & 1) * 8;
    uint32_t b_base0 = smem_base + SMEM_B_OFF + (uint32_t)b_rowoff * (APAD * 2) + b_k8 * 2;

    // ---- pipeline preamble ----
    float4 areg[8];
    ld_a(areg, Xf4, 0, t, block_row);
    cp_b(smem_base, 0, 0, t);
    sts_a(smem_base, t, areg);
    ld_a(areg, Xf4, 1, t, block_row);

#pragma unroll
    for (int c = 0; c < NCHUNK; c++) {
        int cur = c & 1;
        if (c < NCHUNK - 1) {
            sts_a(smem_base + (cur ^ 1) * A_BUF_BYTES, t, areg);
            cp_b(smem_base, c + 1, cur ^ 1, t);
            if (c < NCHUNK - 2) ld_a(areg, Xf4, c + 2, t, block_row);
            asm volatile("cp.async.wait_group 1;" ::: "memory");
        } else {
            asm volatile("cp.async.wait_group 0;" ::: "memory");
        }
        __syncthreads();

        uint32_t a_base = a_base0 + cur * A_BUF_BYTES;
        uint32_t b_base = b_base0 + cur * B_BUF_BYTES;
#pragma unroll
        for (int kk = 0; kk < 4; kk++) {
            uint32_t af[2][4];
#pragma unroll
            for (int mg = 0; mg < 2; mg++) {
                asm volatile("ldmatrix.sync.aligned.m8n8.x4.shared.b16 {%0,%1,%2,%3}, [%4];"
                             : "=r"(af[mg][0]), "=r"(af[mg][1]), "=r"(af[mg][2]), "=r"(af[mg][3])
                             : "r"(a_base + (uint32_t)mg * 16 * (APAD * 2) + kk * 32));
            }
#pragma unroll
            for (int nb = 0; nb < 2; nb++) {
                uint32_t b0, b1, b2, b3;
                asm volatile("ldmatrix.sync.aligned.m8n8.x4.shared.b16 {%0,%1,%2,%3}, [%4];"
                             : "=r"(b0), "=r"(b1), "=r"(b2), "=r"(b3)
                             : "r"(b_base + (uint32_t)nb * 16 * (APAD * 2) + kk * 32));
#pragma unroll
                for (int mg = 0; mg < 2; mg++) {
                    int i0 = mg * 4 + nb * 2;
                    asm volatile("mma.sync.aligned.m16n8k16.row.col.f32.f16.f16.f32 "
                                 "{%0,%1,%2,%3}, {%4,%5,%6,%7}, {%8,%9}, {%0,%1,%2,%3};"
                                 : "+f"(acc[i0][0]), "+f"(acc[i0][1]),
                                   "+f"(acc[i0][2]), "+f"(acc[i0][3])
                                 : "r"(af[mg][0]), "r"(af[mg][1]), "r"(af[mg][2]), "r"(af[mg][3]),
                                   "r"(b0), "r"(b1));
                    asm volatile("mma.sync.aligned.m16n8k16.row.col.f32.f16.f16.f32 "
                                 "{%0,%1,%2,%3}, {%4,%5,%6,%7}, {%8,%9}, {%0,%1,%2,%3};"
                                 : "+f"(acc[i0 + 1][0]), "+f"(acc[i0 + 1][1]),
                                   "+f"(acc[i0 + 1][2]), "+f"(acc[i0 + 1][3])
                                 : "r"(af[mg][0]), "r"(af[mg][1]), "r"(af[mg][2]), "r"(af[mg][3]),
                                   "r"(b2), "r"(b3));
                }
            }
        }
        __syncthreads();
    }

    // epilogue: frag (mg, idx=nb*2+tt): rows wm*32+mg*16+(lane>>2) (+8), half2 col wn*16+idx*4+(lane&3)
    int cquad = lane & 3;
#pragma unroll
    for (int mg = 0; mg < 2; mg++) {
        int r0 = block_row + wm * 32 + mg * 16 + (lane >> 2);
#pragma unroll
        for (int idx = 0; idx < 4; idx++) {
            int i0 = mg * 4 + idx;
            __half2 lo = __floats2half2_rn(acc[i0][0], acc[i0][1]);
            __half2 hi = __floats2half2_rn(acc[i0][2], acc[i0][3]);
            int colh = wn * 16 + idx * 4 + cquad;
            if (r0 < N_NODES)     g_hh0[(size_t)r0 * 32 + colh] = lo;
            if (r0 + 8 < N_NODES) g_hh0[(size_t)(r0 + 8) * 32 + colh] = hi;
        }
    }
}

// ---------------- SpMM layer 1: smem-broadcast edges, gather fp16 ----------------
__global__ void __launch_bounds__(256) spmm1_kernel() {
    __shared__ uint2 stage[8][32];
    const __half2* __restrict__ hin = g_hh0;
    __half2* __restrict__ hout = g_hh1;

    int warp_global = (blockIdx.x * blockDim.x + threadIdx.x) >> 5;
    int wid = (threadIdx.x >> 5) & 7;
    int lane = threadIdx.x & 31;
    if (warp_global >= N_NODES) return;
    int r = warp_global;

    int start = g_row_start[r];
    int end   = g_row_start[r + 1];

    float ax = 0.f, ay = 0.f;
    int e = start;
    while (e + 32 <= end) {
        stage[wid][lane] = g_csr[e + lane];
        __syncwarp();
#pragma unroll
        for (int j = 0; j < 32; j++) {
            uint2 p = stage[wid][j];
            float2 g = __half22float2(__ldg(&hin[(int)p.x * 32 + lane]));
            float v = __uint_as_float(p.y);
            ax = fmaf(v, g.x, ax);
            ay = fmaf(v, g.y, ay);
        }
        __syncwarp();
        e += 32;
    }
    int n = end - e;
    if (n > 0) {
        if (lane < n) stage[wid][lane] = g_csr[e + lane];
        __syncwarp();
        for (int j = 0; j < n; j++) {
            uint2 p = stage[wid][j];
            float2 g = __half22float2(__ldg(&hin[(int)p.x * 32 + lane]));
            float v = __uint_as_float(p.y);
            ax = fmaf(v, g.x, ax);
            ay = fmaf(v, g.y, ay);
        }
    }
    hout[r * 32 + lane] = __floats2half2_rn(ax, ay);
}

// ---------------- SpMM layer 2 fused with bias + log_softmax ----------------
__global__ void __launch_bounds__(256) spmm2_final_kernel(const float* __restrict__ bias,
                                                          float* __restrict__ out) {
    __shared__ uint2 stage[8][32];
    const __half2* __restrict__ hin = g_hh1;

    int warp_global = (blockIdx.x * blockDim.x + threadIdx.x) >> 5;
    int wid = (threadIdx.x >> 5) & 7;
    int lane = threadIdx.x & 31;
    if (warp_global >= N_NODES) return;
    int r = warp_global;

    int start = g_row_start[r];
    int end   = g_row_start[r + 1];

    float ax = 0.f, ay = 0.f;
    int e = start;
    while (e + 32 <= end) {
        stage[wid][lane] = g_csr[e + lane];
        __syncwarp();
#pragma unroll
        for (int j = 0; j < 32; j++) {
            uint2 p = stage[wid][j];
            float2 g = __half22float2(__ldg(&hin[(int)p.x * 32 + lane]));
            float v = __uint_as_float(p.y);
            ax = fmaf(v, g.x, ax);
            ay = fmaf(v, g.y, ay);
        }
        __syncwarp();
        e += 32;
    }
    int n = end - e;
    if (n > 0) {
        if (lane < n) stage[wid][lane] = g_csr[e + lane];
        __syncwarp();
        for (int j = 0; j < n; j++) {
            uint2 p = stage[wid][j];
            float2 g = __half22float2(__ldg(&hin[(int)p.x * 32 + lane]));
            float v = __uint_as_float(p.y);
            ax = fmaf(v, g.x, ax);
            ay = fmaf(v, g.y, ay);
        }
    }

    float2 b = ((const float2*)bias)[lane];
    ax += b.x;
    ay += b.y;

    float mx = fmaxf(ax, ay);
#pragma unroll
    for (int o = 16; o; o >>= 1) mx = fmaxf(mx, __shfl_xor_sync(0xffffffffu, mx, o));
    float s = expf(ax - mx) + expf(ay - mx);
#pragma unroll
    for (int o = 16; o; o >>= 1) s += __shfl_xor_sync(0xffffffffu, s, o);
    float lg = mx + logf(s);

    ((float2*)out)[r * 32 + lane] = make_float2(ax - lg, ay - lg);
}

// ---------------- launch ----------------
extern "C" void kernel_launch(void* const* d_in, const int* in_sizes, int n_in,
                              void* d_out, int out_size) {
    const float* x    = (const float*)d_in[0];
    const float* w    = (const float*)d_in[1];
    const float* bias = (const float*)d_in[2];
    const int*   erow = (const int*)d_in[3];
    const int*   ecol = (const int*)d_in[4];
    const float* eval = (const float*)d_in[5];
    // d_in[6] = nlayers (fixed at 2 by setup_inputs)

    cudaFuncSetAttribute(gemm_mma_kernel,
                         cudaFuncAttributeMaxDynamicSharedMemorySize, GEMM_SMEM);

    hist_wconv_kernel<<<64 + HIST_BLOCKS, 256>>>(erow, w);                // 1
    scan_pass1_kernel<<<25, 1024>>>();                                    // 2
    scan_pass23_kernel<<<25, 1024>>>();                                   // 3
    gemm_mma_kernel<<<(N_NODES + GBM - 1) / GBM, 256, GEMM_SMEM>>>(x);    // 4 <- profiled
    fill_kernel<<<HIST_BLOCKS, 256>>>(erow, ecol, eval);                  // 5

    int warps_grid = (N_NODES * 32 + 255) / 256;  // 12500 blocks
    spmm1_kernel<<<warps_grid, 256>>>();                                  // 6
    spmm2_final_kernel<<<warps_grid, 256>>>(bias, (float*)d_out);         // 7
}

// round 13
// speedup vs baseline: 1.4130x; 1.4130x over previous
#include <cuda_runtime.h>
#include <cuda_fp16.h>
#include <cstdint>

#define N_NODES 100000
#define N_FEAT  512
#define N_CLASS 64
#define N_EDGES 3200000

#define GBM 128           // GEMM rows per CTA
#define NCHUNK 8          // 512/64
#define APAD 72           // padded halves per A/B smem row (144B, conflict-free)

#define A_BUF_BYTES (GBM * APAD * 2)       // 18432
#define B_BUF_BYTES (N_CLASS * APAD * 2)   //  9216
#define SMEM_B_OFF  (2 * A_BUF_BYTES)      // 36864
#define GEMM_SMEM   (2 * A_BUF_BYTES + 2 * B_BUF_BYTES)  // 55296

#define HIST_BLOCKS ((N_EDGES + 255) / 256)   // 12500

// ---------------- scratch (static device globals; zero-initialized) ----------------
__device__ __half2  g_hh0[(size_t)N_NODES * 32];    // 12.8 MB
__device__ __half2  g_hh1[(size_t)N_NODES * 32];    // 12.8 MB
__device__ __half2  g_wt[64 * 256];                 // Wt[n][k] fp16: 64 x 512 (64 KB)
__device__ int   g_count[N_NODES];                  // zero at load; self-cleared each launch
__device__ int   g_row_start[N_NODES + 1];
__device__ int   g_cursor[N_NODES];
__device__ uint2 g_csr[N_EDGES];
__device__ int   g_block_sums[64];

// ---------------- edge histogram ----------------
__global__ void hist_kernel(const int* __restrict__ erow) {
    int e = blockIdx.x * blockDim.x + threadIdx.x;
    if (e < N_EDGES) atomicAdd(&g_count[erow[e]], 1);
}

// ---------------- W [K][N] -> Wt [N][K] fp16 ----------------
__global__ void wconv_kernel(const float* __restrict__ W) {
    int idx = blockIdx.x * blockDim.x + threadIdx.x;   // 0..16383
    int n  = idx >> 8;          // 0..63
    int k2 = idx & 255;         // pairs of k
    int k = k2 * 2;
    float w0 = W[(size_t)k * N_CLASS + n];
    float w1 = W[(size_t)(k + 1) * N_CLASS + n];
    g_wt[n * 256 + k2] = __floats2half2_rn(w0, w1);
}

// ---------------- scan pass1: per-block sums (25 blocks x 1024 x 4) ----------------
__global__ void scan_pass1_kernel() {
    __shared__ int wsum[32];
    int t = threadIdx.x;
    int base = blockIdx.x * 4096;
    int s = 0;
#pragma unroll
    for (int i = 0; i < 4; i++) {
        int idx = base + t * 4 + i;
        if (idx < N_NODES) s += g_count[idx];
    }
#pragma unroll
    for (int o = 16; o; o >>= 1) s += __shfl_down_sync(0xffffffffu, s, o);
    if ((t & 31) == 0) wsum[t >> 5] = s;
    __syncthreads();
    if (t < 32) {
        int v = wsum[t];
#pragma unroll
        for (int o = 16; o; o >>= 1) v += __shfl_down_sync(0xffffffffu, v, o);
        if (t == 0) g_block_sums[blockIdx.x] = v;
    }
}

// ---------------- scan pass2+3 merged ----------------
__global__ void scan_pass23_kernel() {
    __shared__ int woff[32];
    __shared__ int s_boff;
    int t = threadIdx.x, lane = t & 31, wid = t >> 5;

    if (t < 32) {
        int v = (t < 25) ? g_block_sums[t] : 0;
        int x = v;
#pragma unroll
        for (int o = 1; o < 32; o <<= 1) {
            int y = __shfl_up_sync(0xffffffffu, x, o);
            if (t >= o) x += y;
        }
        if (t == (int)blockIdx.x) s_boff = x - v;
        if (blockIdx.x == 0 && t == 24) g_row_start[N_NODES] = x;
    }
    __syncthreads();

    int base = blockIdx.x * 4096;
    int v[4];
    int s = 0;
#pragma unroll
    for (int i = 0; i < 4; i++) {
        int idx = base + t * 4 + i;
        if (idx < N_NODES) {
            v[i] = g_count[idx];
            g_count[idx] = 0;        // self-clear for deterministic replays
        } else v[i] = 0;
        s += v[i];
    }
    int x = s;
#pragma unroll
    for (int o = 1; o < 32; o <<= 1) {
        int y = __shfl_up_sync(0xffffffffu, x, o);
        if (lane >= o) x += y;
    }
    if (lane == 31) woff[wid] = x;
    __syncthreads();
    if (wid == 0) {
        int w = woff[lane];
        int xw = w;
#pragma unroll
        for (int o = 1; o < 32; o <<= 1) {
            int y = __shfl_up_sync(0xffffffffu, xw, o);
            if (lane >= o) xw += y;
        }
        woff[lane] = xw - w;
    }
    __syncthreads();
    int off = s_boff + woff[wid] + (x - s);
#pragma unroll
    for (int i = 0; i < 4; i++) {
        int idx = base + t * 4 + i;
        if (idx < N_NODES) {
            g_row_start[idx] = off;
            g_cursor[idx] = off;
        }
        off += v[i];
    }
}

__global__ void fill_kernel(const int* __restrict__ erow,
                            const int* __restrict__ ecol,
                            const float* __restrict__ eval) {
    int e = blockIdx.x * blockDim.x + threadIdx.x;
    if (e < N_EDGES) {
        int pos = atomicAdd(&g_cursor[erow[e]], 1);
        g_csr[pos] = make_uint2((unsigned)ecol[e], __float_as_uint(eval[e]));
    }
}

// ---------------- pipelined HMMA GEMM, 32x32 warp tiles, coalesced A loads ----------------
__device__ __forceinline__ void ld_a(float4* areg, const float4* __restrict__ Xf4,
                                     int c, int t, int block_row) {
#pragma unroll
    for (int i = 0; i < 8; i++) {
        int f4 = t + 256 * i;
        int row = f4 >> 4, c4 = f4 & 15;
        int gr = block_row + row;
        areg[i] = (gr < N_NODES) ? Xf4[(size_t)gr * 128 + c * 16 + c4]
                                 : make_float4(0.f, 0.f, 0.f, 0.f);
    }
}

__device__ __forceinline__ void sts_a(uint32_t abuf_base, int t, const float4* areg) {
#pragma unroll
    for (int i = 0; i < 8; i++) {
        int f4 = t + 256 * i;
        int row = f4 >> 4, c4 = f4 & 15;
        __half2 q0 = __floats2half2_rn(areg[i].x, areg[i].y);
        __half2 q1 = __floats2half2_rn(areg[i].z, areg[i].w);
        uint32_t addr = abuf_base + (uint32_t)row * (APAD * 2) + c4 * 8;
        asm volatile("st.shared.v2.b32 [%0], {%1, %2};"
                     :: "r"(addr), "r"(*(uint32_t*)&q0), "r"(*(uint32_t*)&q1)
                     : "memory");
    }
}

__device__ __forceinline__ void cp_b(uint32_t smem_base, int c, int buf, int t) {
    int n  = t >> 2;
    int sg = t & 3;
    const __half2* src = g_wt + n * 256 + c * 32 + sg * 4;
    uint32_t dst = smem_base + SMEM_B_OFF + buf * B_BUF_BYTES
                 + (uint32_t)n * (APAD * 2) + sg * 16;
    asm volatile("cp.async.ca.shared.global [%0], [%1], 16;" :: "r"(dst), "l"(src) : "memory");
    asm volatile("cp.async.ca.shared.global [%0], [%1], 16;" :: "r"(dst + 64), "l"(src + 16) : "memory");
    asm volatile("cp.async.commit_group;" ::: "memory");
}

__global__ void __launch_bounds__(256, 2) gemm_mma_kernel(const float* __restrict__ X) {
    extern __shared__ __align__(16) unsigned char smem_raw[];
    uint32_t smem_base;
    asm("{ .reg .u64 t; cvta.to.shared.u64 t, %1; cvt.u32.u64 %0, t; }"
        : "=r"(smem_base) : "l"(smem_raw));

    int t = threadIdx.x;
    int wid = t >> 5, lane = t & 31;
    int block_row = blockIdx.x * GBM;
    const float4* Xf4 = (const float4*)X;

    int wm = wid >> 1, wn = wid & 1;

    float acc[8][4];
#pragma unroll
    for (int i = 0; i < 8; i++)
#pragma unroll
        for (int j = 0; j < 4; j++) acc[i][j] = 0.f;

    int a_row = wm * 32 + ((lane >> 3) & 1) * 8 + (lane & 7);
    int a_k8  = (lane >> 4) * 8;
    uint32_t a_base0 = smem_base + (uint32_t)a_row * (APAD * 2) + a_k8 * 2;
    int b_q = lane >> 3, b_l = lane & 7;
    int b_rowoff = wn * 32 + (b_q >> 1) * 8 + b_l;
    int b_k8 = (b_q & 1) * 8;
    uint32_t b_base0 = smem_base + SMEM_B_OFF + (uint32_t)b_rowoff * (APAD * 2) + b_k8 * 2;

    float4 areg[8];
    ld_a(areg, Xf4, 0, t, block_row);
    cp_b(smem_base, 0, 0, t);
    sts_a(smem_base, t, areg);
    ld_a(areg, Xf4, 1, t, block_row);

#pragma unroll
    for (int c = 0; c < NCHUNK; c++) {
        int cur = c & 1;
        if (c < NCHUNK - 1) {
            sts_a(smem_base + (cur ^ 1) * A_BUF_BYTES, t, areg);
            cp_b(smem_base, c + 1, cur ^ 1, t);
            if (c < NCHUNK - 2) ld_a(areg, Xf4, c + 2, t, block_row);
            asm volatile("cp.async.wait_group 1;" ::: "memory");
        } else {
            asm volatile("cp.async.wait_group 0;" ::: "memory");
        }
        __syncthreads();

        uint32_t a_base = a_base0 + cur * A_BUF_BYTES;
        uint32_t b_base = b_base0 + cur * B_BUF_BYTES;
#pragma unroll
        for (int kk = 0; kk < 4; kk++) {
            uint32_t af[2][4];
#pragma unroll
            for (int mg = 0; mg < 2; mg++) {
                asm volatile("ldmatrix.sync.aligned.m8n8.x4.shared.b16 {%0,%1,%2,%3}, [%4];"
                             : "=r"(af[mg][0]), "=r"(af[mg][1]), "=r"(af[mg][2]), "=r"(af[mg][3])
                             : "r"(a_base + (uint32_t)mg * 16 * (APAD * 2) + kk * 32));
            }
#pragma unroll
            for (int nb = 0; nb < 2; nb++) {
                uint32_t b0, b1, b2, b3;
                asm volatile("ldmatrix.sync.aligned.m8n8.x4.shared.b16 {%0,%1,%2,%3}, [%4];"
                             : "=r"(b0), "=r"(b1), "=r"(b2), "=r"(b3)
                             : "r"(b_base + (uint32_t)nb * 16 * (APAD * 2) + kk * 32));
#pragma unroll
                for (int mg = 0; mg < 2; mg++) {
                    int i0 = mg * 4 + nb * 2;
                    asm volatile("mma.sync.aligned.m16n8k16.row.col.f32.f16.f16.f32 "
                                 "{%0,%1,%2,%3}, {%4,%5,%6,%7}, {%8,%9}, {%0,%1,%2,%3};"
                                 : "+f"(acc[i0][0]), "+f"(acc[i0][1]),
                                   "+f"(acc[i0][2]), "+f"(acc[i0][3])
                                 : "r"(af[mg][0]), "r"(af[mg][1]), "r"(af[mg][2]), "r"(af[mg][3]),
                                   "r"(b0), "r"(b1));
                    asm volatile("mma.sync.aligned.m16n8k16.row.col.f32.f16.f16.f32 "
                                 "{%0,%1,%2,%3}, {%4,%5,%6,%7}, {%8,%9}, {%0,%1,%2,%3};"
                                 : "+f"(acc[i0 + 1][0]), "+f"(acc[i0 + 1][1]),
                                   "+f"(acc[i0 + 1][2]), "+f"(acc[i0 + 1][3])
                                 : "r"(af[mg][0]), "r"(af[mg][1]), "r"(af[mg][2]), "r"(af[mg][3]),
                                   "r"(b2), "r"(b3));
                }
            }
        }
        __syncthreads();
    }

    int cquad = lane & 3;
#pragma unroll
    for (int mg = 0; mg < 2; mg++) {
        int r0 = block_row + wm * 32 + mg * 16 + (lane >> 2);
#pragma unroll
        for (int idx = 0; idx < 4; idx++) {
            int i0 = mg * 4 + idx;
            __half2 lo = __floats2half2_rn(acc[i0][0], acc[i0][1]);
            __half2 hi = __floats2half2_rn(acc[i0][2], acc[i0][3]);
            int colh = wn * 16 + idx * 4 + cquad;
            if (r0 < N_NODES)     g_hh0[(size_t)r0 * 32 + colh] = lo;
            if (r0 + 8 < N_NODES) g_hh0[(size_t)(r0 + 8) * 32 + colh] = hi;
        }
    }
}

// ---------------- SpMM layer 1: smem-broadcast edges, gather fp16 ----------------
__global__ void __launch_bounds__(256) spmm1_kernel() {
    __shared__ uint2 stage[8][32];
    const __half2* __restrict__ hin = g_hh0;
    __half2* __restrict__ hout = g_hh1;

    int warp_global = (blockIdx.x * blockDim.x + threadIdx.x) >> 5;
    int wid = (threadIdx.x >> 5) & 7;
    int lane = threadIdx.x & 31;
    if (warp_global >= N_NODES) return;
    int r = warp_global;

    int start = g_row_start[r];
    int end   = g_row_start[r + 1];

    float ax = 0.f, ay = 0.f;
    int e = start;
    while (e + 32 <= end) {
        stage[wid][lane] = g_csr[e + lane];
        __syncwarp();
#pragma unroll
        for (int j = 0; j < 32; j++) {
            uint2 p = stage[wid][j];
            float2 g = __half22float2(__ldg(&hin[(int)p.x * 32 + lane]));
            float v = __uint_as_float(p.y);
            ax = fmaf(v, g.x, ax);
            ay = fmaf(v, g.y, ay);
        }
        __syncwarp();
        e += 32;
    }
    int n = end - e;
    if (n > 0) {
        if (lane < n) stage[wid][lane] = g_csr[e + lane];
        __syncwarp();
        for (int j = 0; j < n; j++) {
            uint2 p = stage[wid][j];
            float2 g = __half22float2(__ldg(&hin[(int)p.x * 32 + lane]));
            float v = __uint_as_float(p.y);
            ax = fmaf(v, g.x, ax);
            ay = fmaf(v, g.y, ay);
        }
    }
    hout[r * 32 + lane] = __floats2half2_rn(ax, ay);
}

// ---------------- SpMM layer 2 fused with bias + log_softmax ----------------
__global__ void __launch_bounds__(256) spmm2_final_kernel(const float* __restrict__ bias,
                                                          float* __restrict__ out) {
    __shared__ uint2 stage[8][32];
    const __half2* __restrict__ hin = g_hh1;

    int warp_global = (blockIdx.x * blockDim.x + threadIdx.x) >> 5;
    int wid = (threadIdx.x >> 5) & 7;
    int lane = threadIdx.x & 31;
    if (warp_global >= N_NODES) return;
    int r = warp_global;

    int start = g_row_start[r];
    int end   = g_row_start[r + 1];

    float ax = 0.f, ay = 0.f;
    int e = start;
    while (e + 32 <= end) {
        stage[wid][lane] = g_csr[e + lane];
        __syncwarp();
#pragma unroll
        for (int j = 0; j < 32; j++) {
            uint2 p = stage[wid][j];
            float2 g = __half22float2(__ldg(&hin[(int)p.x * 32 + lane]));
            float v = __uint_as_float(p.y);
            ax = fmaf(v, g.x, ax);
            ay = fmaf(v, g.y, ay);
        }
        __syncwarp();
        e += 32;
    }
    int n = end - e;
    if (n > 0) {
        if (lane < n) stage[wid][lane] = g_csr[e + lane];
        __syncwarp();
        for (int j = 0; j < n; j++) {
            uint2 p = stage[wid][j];
            float2 g = __half22float2(__ldg(&hin[(int)p.x * 32 + lane]));
            float v = __uint_as_float(p.y);
            ax = fmaf(v, g.x, ax);
            ay = fmaf(v, g.y, ay);
        }
    }

    float2 b = ((const float2*)bias)[lane];
    ax += b.x;
    ay += b.y;

    float mx = fmaxf(ax, ay);
#pragma unroll
    for (int o = 16; o; o >>= 1) mx = fmaxf(mx, __shfl_xor_sync(0xffffffffu, mx, o));
    float s = expf(ax - mx) + expf(ay - mx);
#pragma unroll
    for (int o = 16; o; o >>= 1) s += __shfl_xor_sync(0xffffffffu, s, o);
    float lg = mx + logf(s);

    ((float2*)out)[r * 32 + lane] = make_float2(ax - lg, ay - lg);
}

// ---------------- launch: fork-join concurrency inside graph capture ----------------
// Chain A (side stream): wconv -> gemm            (~82us, needs only W/X)
// Chain B (main stream): hist -> scans -> fill    (~55us, needs only edges)
// Join, then spmm1 -> spmm2. Streams/events are created per call and not
// destroyed (kernel_launch runs only for correctness + capture; no device
// memory is allocated by stream/event creation).
extern "C" void kernel_launch(void* const* d_in, const int* in_sizes, int n_in,
                              void* d_out, int out_size) {
    const float* x    = (const float*)d_in[0];
    const float* w    = (const float*)d_in[1];
    const float* bias = (const float*)d_in[2];
    const int*   erow = (const int*)d_in[3];
    const int*   ecol = (const int*)d_in[4];
    const float* eval = (const float*)d_in[5];
    // d_in[6] = nlayers (fixed at 2 by setup_inputs)

    cudaFuncSetAttribute(gemm_mma_kernel,
                         cudaFuncAttributeMaxDynamicSharedMemorySize, GEMM_SMEM);

    cudaStream_t s2;
    cudaStreamCreateWithFlags(&s2, cudaStreamNonBlocking);
    cudaEvent_t ev_fork, ev_join;
    cudaEventCreateWithFlags(&ev_fork, cudaEventDisableTiming);
    cudaEventCreateWithFlags(&ev_join, cudaEventDisableTiming);

    // fork
    cudaEventRecord(ev_fork, 0);
    cudaStreamWaitEvent(s2, ev_fork, 0);

    // chain A on s2: wconv -> gemm
    wconv_kernel<<<64, 256, 0, s2>>>(w);
    gemm_mma_kernel<<<(N_NODES + GBM - 1) / GBM, 256, GEMM_SMEM, s2>>>(x);

    // chain B on main stream: CSR build
    hist_kernel<<<HIST_BLOCKS, 256>>>(erow);
    scan_pass1_kernel<<<25, 1024>>>();
    scan_pass23_kernel<<<25, 1024>>>();
    fill_kernel<<<HIST_BLOCKS, 256>>>(erow, ecol, eval);

    // join
    cudaEventRecord(ev_join, s2);
    cudaStreamWaitEvent(0, ev_join, 0);

    int warps_grid = (N_NODES * 32 + 255) / 256;  // 12500 blocks
    spmm1_kernel<<<warps_grid, 256>>>();
    spmm2_final_kernel<<<warps_grid, 256>>>(bias, (float*)d_out);
}